// round 14
// baseline (speedup 1.0000x reference)
#include <cuda_runtime.h>

typedef unsigned long long u64;

// ---- packed f32x2 helpers (sm_103a) ----
__device__ __forceinline__ u64 fma2(u64 a, u64 b, u64 c) {
    u64 d;
    asm("fma.rn.f32x2 %0, %1, %2, %3;" : "=l"(d) : "l"(a), "l"(b), "l"(c));
    return d;
}
__device__ __forceinline__ u64 mul2(u64 a, u64 b) {
    u64 d;
    asm("mul.rn.f32x2 %0, %1, %2;" : "=l"(d) : "l"(a), "l"(b));
    return d;
}
__device__ __forceinline__ u64 add2(u64 a, u64 b) {
    u64 d;
    asm("add.rn.f32x2 %0, %1, %2;" : "=l"(d) : "l"(a), "l"(b));
    return d;
}
__device__ __forceinline__ u64 relu2(u64 v) {
    unsigned a, b;
    asm("mov.b64 {%0, %1}, %2;" : "=r"(a), "=r"(b) : "l"(v));
    float lo = fmaxf(__uint_as_float(a), 0.0f);
    float hi = fmaxf(__uint_as_float(b), 0.0f);
    u64 d;
    asm("mov.b64 %0, {%1, %2};" : "=l"(d) : "r"(__float_as_uint(lo)), "r"(__float_as_uint(hi)));
    return d;
}
__device__ __forceinline__ u64 lds64(unsigned a) {
    u64 v;
    asm volatile("ld.shared.b64 %0, [%1];" : "=l"(v) : "r"(a));
    return v;
}
__device__ __forceinline__ void sts64(unsigned a, u64 v) {
    asm volatile("st.shared.b64 [%0], %1;" :: "r"(a), "l"(v));
}

// ---- problem constants ----
constexpr int W_DIM = 4096;
constexpr int C_DIM = 64;
constexpr int L_SEG = 256;              // outputs per segment
constexpr int SEGS  = W_DIM / L_SEG;    // 16
constexpr int BH    = 16 * 21;          // 336 rows
constexpr int N_SEG = BH * SEGS;        // 5376 segments (one per 2-warp block)
constexpr int N_IT  = (64 + L_SEG) / 32;              // 10 iterations
constexpr int DEPTH_X = 2;              // cp.async x-ring depth
constexpr int XBLK  = 32 * 256;         // 8 KB per 32-position x block
constexpr int YBLK  = 32 * 256;         // 8 KB per 32-step y2 block
constexpr int YDEPTH = 3;               // y2 smem ring depth
constexpr int SMEM_X = DEPTH_X * XBLK;                // 16 KB
constexpr int SMEM_TOTAL = SMEM_X + YDEPTH * YBLK;    // 40 KB per block

// Named barriers (per-CTA): A produces y2, B consumes.
// READY: A bar.arrive after writing block k; B bar.sync before reading block k.
// FREE : B bar.arrive after finishing block m (m>=1; means blocks <= m-1 fully
//        consumed since block b is last read during B's block b+1);
//        A bar.sync before writing block k>=3 (clobbers slot k-3; sync #(k-3)
//        pairs with B's arrive for block k-2 -> block k-3 free).
#define BAR_ARRIVE(id) asm volatile("bar.arrive %0, 64;" :: "r"(id) : "memory")
#define BAR_SYNC64(id) asm volatile("bar.sync %0, 64;"   :: "r"(id) : "memory")
constexpr int BAR_READY = 1;
constexpr int BAR_FREE  = 2;

// Cross-correlation, zero pad. pad_lo: d=1 -> 3, d=2 -> 7, d=4 -> 14.
// y1[w] = relu(sum_k x [w- 3+  k] * w1[k])
// y2[w] = relu(sum_k y1[w- 7+ 2k] * w2[k])   (y1 := 0 outside [0,W))
// y3[w] = relu(sum_k y2[w-14+ 4k] * w3[k])   (y2 := 0 outside [0,W))
//
// Warp-specialized pipeline (R14). t0 = s0-36. "step i" (block k=i/32, u=i&31):
//  Warp A: LDS x pos t0+i+8 (8-step lead) -> xr[(u+8)&15]
//          STAGE1 y1 @ t0+i-4 -> y1r[u&15]
//          STAGE2 y2 @ t0+i-12 (masked) -> STS to y2 smem ring blk k%3 offs u
//          (block 0: stage2 skipped entirely; stage1 only for u>=16 since the
//           16-slot y1 ring is fully rewritten by steps 16..31 before any use)
//  Warp B: LDS y2 step i -> y2r[u&31] register ring (1 LDS/step; taps in regs)
//          STAGE3 y3 @ t0+i-28 -> STG   (y2 steps i-30..i-2 from reg ring)
//          (block 0: idle; block 1: LDS-only to seed the ring; blocks 2+: full)
// Why: monolithic warp needed 176+ ring regs -> pinned at 255 regs / 8 warps
// /SM with zero ptxas scheduling slack (R6-R10 all spilled when given less).
// Split state: A ~120 regs, B ~95 -> launch_bounds(64,5) budget 204, no spill,
// 10 warps/SM, and real scheduling slack in both warps.

__device__ __forceinline__ void prefetch_blk(const char* gsrc, int p0,
                                             unsigned sdst, int lane)
{
    #pragma unroll
    for (int j = 0; j < 16; ++j) {
        const int idx = j * 32 + lane;           // 16B chunk index in the 8KB blk
        const int p   = p0 + (idx >> 4);         // position this chunk belongs to
        const unsigned ok = (p >= 0 && p < W_DIM) ? 16u : 0u;
        asm volatile("cp.async.cg.shared.global [%0], [%1], 16, %2;"
                     :: "r"(sdst + idx * 16), "l"(gsrc + idx * 16), "r"(ok)
                     : "memory");
    }
    asm volatile("cp.async.commit_group;" ::: "memory");
}

#define LDS_X(u)                                                               \
    {                                                                          \
        xr[((u) + 8) & 15] = lds64(cons + (u) * 256);                          \
    }

#define STAGE1(u)                                                              \
    {                                                                          \
        u64 a0 = mul2(xr[((u) - 7) & 15], w1r[0]);                             \
        u64 a1 = mul2(xr[((u) - 6) & 15], w1r[1]);                             \
        a0 = fma2(xr[((u) - 5) & 15], w1r[2], a0);                             \
        a1 = fma2(xr[((u) - 4) & 15], w1r[3], a1);                             \
        a0 = fma2(xr[((u) - 3) & 15], w1r[4], a0);                             \
        a1 = fma2(xr[((u) - 2) & 15], w1r[5], a1);                             \
        a0 = fma2(xr[((u) - 1) & 15], w1r[6], a0);                             \
        a1 = fma2(xr[((u) - 0) & 15], w1r[7], a1);                             \
        u64 y1v = relu2(add2(a0, a1));                                         \
        if (BOUNDARY) {                                                        \
            const int p1 = pb + (u) - 4;                                       \
            if (p1 < 0 || p1 >= W_DIM) y1v = 0ull;                             \
        }                                                                      \
        y1r[(u) & 15] = y1v;                                                   \
    }

#define STAGE2_STS(u)                                                          \
    {                                                                          \
        u64 b0 = mul2(y1r[((u) - 15) & 15], w2r[0]);                           \
        u64 b1 = mul2(y1r[((u) - 13) & 15], w2r[1]);                           \
        b0 = fma2(y1r[((u) - 11) & 15], w2r[2], b0);                           \
        b1 = fma2(y1r[((u) -  9) & 15], w2r[3], b1);                           \
        b0 = fma2(y1r[((u) -  7) & 15], w2r[4], b0);                           \
        b1 = fma2(y1r[((u) -  5) & 15], w2r[5], b1);                           \
        b0 = fma2(y1r[((u) -  3) & 15], w2r[6], b0);                           \
        b1 = fma2(y1r[((u) -  1) & 15], w2r[7], b1);                           \
        u64 y2v = relu2(add2(b0, b1));                                         \
        if (BOUNDARY) {                                                        \
            const int p2 = pb + (u) - 12;                                      \
            if (p2 < 0 || p2 >= W_DIM) y2v = 0ull;                             \
        }                                                                      \
        sts64(ysl + (u) * 256, y2v);                                           \
    }

#define STAGE3_STORE(u)                                                        \
    {                                                                          \
        u64 c0 = mul2(y2r[((u) - 30) & 31], w3r[0]);                           \
        u64 c1 = mul2(y2r[((u) - 26) & 31], w3r[1]);                           \
        c0 = fma2(y2r[((u) - 22) & 31], w3r[2], c0);                           \
        c1 = fma2(y2r[((u) - 18) & 31], w3r[3], c1);                           \
        c0 = fma2(y2r[((u) - 14) & 31], w3r[4], c0);                           \
        c1 = fma2(y2r[((u) - 10) & 31], w3r[5], c1);                           \
        c0 = fma2(y2r[((u) -  6) & 31], w3r[6], c0);                           \
        c1 = fma2(y2r[((u) -  2) & 31], w3r[7], c1);                           \
        const u64 y3v = relu2(add2(c0, c1));                                   \
        __stcs((u64*)(sp + (u) * C_DIM), y3v);                                 \
    }

template<bool BOUNDARY>
__device__ __forceinline__ void runA(
    const float* __restrict__ x,
    const u64* w1r, const u64* w2r,
    int bh, int seg, int lane, unsigned xring, unsigned yring)
{
    const int s0 = seg * L_SEG;
    const int t0 = s0 - 36;

    const char* gpf = (const char*)x
                    + ((long long)bh * W_DIM + (t0 + 8)) * (C_DIM * 4);
    int ppf = t0 + 8;

    #pragma unroll
    for (int b = 0; b < DEPTH_X; ++b) {
        prefetch_blk(gpf, ppf, xring + b * XBLK, lane);
        gpf += XBLK;
        ppf += 32;
    }

    int pb = t0;

    u64 xr[16], y1r[16];
    #pragma unroll
    for (int j = 0; j < 16; ++j) xr[j]  = 0ull;
    #pragma unroll
    for (int j = 0; j < 16; ++j) y1r[j] = 0ull;

    unsigned cons = xring + lane * 8;
    const unsigned cons_hi = xring + DEPTH_X * XBLK;
    unsigned ysl = yring + lane * 8;
    const unsigned ysl_hi = yring + YDEPTH * YBLK;

    for (int k = 0; k < N_IT; ++k) {
        if (k >= YDEPTH) BAR_SYNC64(BAR_FREE);   // slot k-3 must be consumed

        if (k == N_IT - 1) asm volatile("cp.async.wait_group 0;" ::: "memory");
        else               asm volatile("cp.async.wait_group 1;" ::: "memory");
        __syncwarp();

        if (k == 0) {
            // y1 of steps <16 fully overwritten before first stage2 use
            #pragma unroll
            for (int u = 0; u < 32; ++u) {
                LDS_X(u)
                if (u >= 16) STAGE1(u)
            }
        } else {
            #pragma unroll
            for (int u = 0; u < 32; ++u) {
                LDS_X(u) STAGE1(u) STAGE2_STS(u)
            }
        }

        if (k + DEPTH_X < N_IT) {
            prefetch_blk(gpf, ppf, cons - lane * 8, lane);
            gpf += XBLK;
            ppf += 32;
        }

        BAR_ARRIVE(BAR_READY);                   // y2 block k visible to B

        cons += XBLK; if (cons >= cons_hi) cons -= DEPTH_X * XBLK;
        ysl  += YBLK; if (ysl  >= ysl_hi)  ysl  -= YDEPTH * YBLK;
        pb   += 32;
    }
}

__device__ __forceinline__ void runB(
    float* __restrict__ out, const u64* w3r,
    int bh, int seg, int lane, unsigned yring)
{
    const int s0 = seg * L_SEG;

    float* sp = out + ((long long)bh * W_DIM + s0) * C_DIM + 2 * lane;

    u64 y2r[32];
    #pragma unroll
    for (int j = 0; j < 32; ++j) y2r[j] = 0ull;

    unsigned ysl = yring + lane * 8;
    const unsigned ysl_hi = yring + YDEPTH * YBLK;

    for (int k = 0; k < N_IT; ++k) {
        BAR_SYNC64(BAR_READY);                   // y2 block k ready

        if (k == 1) {
            // seed the register ring with y2 steps 32..63 (block 0 never read)
            #pragma unroll
            for (int u = 0; u < 32; ++u)
                y2r[u] = lds64(ysl + u * 256);
        } else if (k >= 2) {
            #pragma unroll
            for (int u = 0; u < 32; ++u) {
                y2r[u & 31] = lds64(ysl + u * 256);  // y2 step 32k+u
                STAGE3_STORE(u)                       // y3 @ s0+32(k-2)+u
            }
            sp += 32 * C_DIM;
        }

        if (k >= 1) BAR_ARRIVE(BAR_FREE);        // blocks <= k-1 fully consumed

        ysl += YBLK; if (ysl >= ysl_hi) ysl -= YDEPTH * YBLK;
    }
}

__global__ void __launch_bounds__(64, 5)
conv_stack_kernel(const float* __restrict__ x,
                  const float* __restrict__ w1,
                  const float* __restrict__ w2,
                  const float* __restrict__ w3,
                  float* __restrict__ out)
{
    extern __shared__ char smem[];

    const int wib  = threadIdx.x >> 5;            // 0 = producer A, 1 = consumer B
    const int lane = threadIdx.x & 31;

    const unsigned xring = (unsigned)__cvta_generic_to_shared(smem);
    const unsigned yring = xring + SMEM_X;

    const int s   = blockIdx.x;                   // one segment per 2-warp block
    const int bh  = s >> 4;                       // s / SEGS
    const int seg = s & 15;                       // s % SEGS
    const bool bdy = (seg == 0 || seg == SEGS - 1);

    if (wib == 0) {
        u64 w1r[8], w2r[8];
        #pragma unroll
        for (int k = 0; k < 8; ++k) {
            w1r[k] = *(const u64*)(w1 + k * C_DIM + 2 * lane);
            w2r[k] = *(const u64*)(w2 + k * C_DIM + 2 * lane);
        }
        if (bdy) runA<true >(x, w1r, w2r, bh, seg, lane, xring, yring);
        else     runA<false>(x, w1r, w2r, bh, seg, lane, xring, yring);
    } else {
        u64 w3r[8];
        #pragma unroll
        for (int k = 0; k < 8; ++k)
            w3r[k] = *(const u64*)(w3 + k * C_DIM + 2 * lane);
        runB(out, w3r, bh, seg, lane, yring);
    }
}

extern "C" void kernel_launch(void* const* d_in, const int* in_sizes, int n_in,
                              void* d_out, int out_size)
{
    const float* x  = (const float*)d_in[0];
    const float* w1 = (const float*)d_in[1];
    const float* w2 = (const float*)d_in[2];
    const float* w3 = (const float*)d_in[3];
    float* out = (float*)d_out;

    (void)in_sizes; (void)n_in; (void)out_size;

    cudaFuncSetAttribute(conv_stack_kernel,
                         cudaFuncAttributeMaxDynamicSharedMemorySize, SMEM_TOTAL);

    // 5376 segments -> 5376 blocks of 64 threads (A+B pair per segment)
    conv_stack_kernel<<<N_SEG, 64, SMEM_TOTAL>>>(x, w1, w2, w3, out);
}

// round 15
// speedup vs baseline: 1.1383x; 1.1383x over previous
#include <cuda_runtime.h>

typedef unsigned long long u64;

// ---- packed f32x2 helpers (sm_103a) ----
__device__ __forceinline__ u64 fma2(u64 a, u64 b, u64 c) {
    u64 d;
    asm("fma.rn.f32x2 %0, %1, %2, %3;" : "=l"(d) : "l"(a), "l"(b), "l"(c));
    return d;
}
__device__ __forceinline__ u64 mul2(u64 a, u64 b) {
    u64 d;
    asm("mul.rn.f32x2 %0, %1, %2;" : "=l"(d) : "l"(a), "l"(b));
    return d;
}
__device__ __forceinline__ u64 add2(u64 a, u64 b) {
    u64 d;
    asm("add.rn.f32x2 %0, %1, %2;" : "=l"(d) : "l"(a), "l"(b));
    return d;
}
__device__ __forceinline__ u64 relu2(u64 v) {
    unsigned a, b;
    asm("mov.b64 {%0, %1}, %2;" : "=r"(a), "=r"(b) : "l"(v));
    float lo = fmaxf(__uint_as_float(a), 0.0f);
    float hi = fmaxf(__uint_as_float(b), 0.0f);
    u64 d;
    asm("mov.b64 %0, {%1, %2};" : "=l"(d) : "r"(__float_as_uint(lo)), "r"(__float_as_uint(hi)));
    return d;
}
__device__ __forceinline__ u64 lds64(unsigned a) {
    u64 v;
    asm volatile("ld.shared.b64 %0, [%1];" : "=l"(v) : "r"(a));
    return v;
}

// ---- mbarrier / bulk-TMA helpers ----
#define MBAR_INIT(a)                                                           \
    asm volatile("mbarrier.init.shared.b64 [%0], 1;" :: "r"(a) : "memory")
#define MBAR_FENCE_INIT()                                                      \
    asm volatile("fence.mbarrier_init.release.cluster;" ::: "memory")
#define MBAR_EXPECT(a, bytes)                                                  \
    asm volatile("mbarrier.arrive.expect_tx.shared.b64 _, [%0], %1;"           \
                 :: "r"(a), "r"(bytes) : "memory")
#define TMA_BULK(sdst, gsrc, bytes, mbar)                                      \
    asm volatile("cp.async.bulk.shared::cluster.global.mbarrier::complete_tx::bytes " \
                 "[%0], [%1], %2, [%3];"                                       \
                 :: "r"(sdst), "l"(gsrc), "r"(bytes), "r"(mbar) : "memory")
#define MBAR_WAIT(a, p)                                                        \
    asm volatile(                                                              \
        "{\n\t"                                                                \
        ".reg .pred P1;\n\t"                                                   \
        "WAIT_LOOP_%=:\n\t"                                                    \
        "mbarrier.try_wait.parity.acquire.cta.shared::cta.b64 P1, [%0], %1, 0x989680;\n\t" \
        "@P1 bra.uni WAIT_DONE_%=;\n\t"                                        \
        "bra.uni WAIT_LOOP_%=;\n\t"                                            \
        "WAIT_DONE_%=:\n\t"                                                    \
        "}"                                                                    \
        :: "r"(a), "r"(p) : "memory")

// ---- problem constants ----
constexpr int W_DIM = 4096;
constexpr int C_DIM = 64;
constexpr int L_SEG = 256;              // outputs per segment
constexpr int SEGS  = W_DIM / L_SEG;    // 16
constexpr int BH    = 16 * 21;          // 336 rows
constexpr int N_SEG = BH * SEGS;        // 5376 segments
constexpr int WU_IT = 2;                // warmup iterations (64 steps)
constexpr int N_IT  = (64 + L_SEG) / 32;              // 10 iterations
constexpr int DEPTH = 3;                // x ring depth (blocks)
constexpr int BLK_BYTES = 32 * 256;     // 32 positions x 256 B = 8 KB
constexpr int MB_OFF = DEPTH * BLK_BYTES;             // mbarriers after slots
constexpr int WARP_SMEM = MB_OFF + 64;                // 24 KB + mbar pad

// Cross-correlation, zero pad. pad_lo: d=1 -> 3, d=2 -> 7, d=4 -> 14.
// y1[w] = relu(sum_k x [w- 3+  k] * w1[k])
// y2[w] = relu(sum_k y1[w- 7+ 2k] * w2[k])   (y1 := 0 outside [0,W))
// y3[w] = relu(sum_k y2[w-14+ 4k] * w3[k])   (y2 := 0 outside [0,W))
//
// Proven schedule (R12, 163 us): per warp, lane = 2 packed channels, t0=s0-36.
// smem blk b holds positions t0+8+32b .. t0+39+32b (8 KB, gmem-contiguous).
// step i (iter k = i/32, u = i&31):
//   LDS    x pos t0+i+8 from blk k, offs u  -> xr[(u+8)&15]  (8-step lead)
//   STAGE1 y1 @ t0+i-4   -> y1r[u&15]     (x slots i-7..i)
//   STAGE2 y2 @ t0+i-12  -> y2r[u&31]     (y1 steps i-15..i-1, 1-step lag)
//   STAGE3 y3 @ t0+i-28  -> STG           (y2 steps i-30..i-2, 2-step lag)
// MUST stay at 255-reg budget: lower budgets demote y2r[32] to local mem.
//
// R15 single change vs R12: INTERIOR segments (fully in-bounds) feed the x
// ring with ONE cp.async.bulk (8 KB) + mbarrier per iteration instead of
// 16 LDGSTS + commit + wait_group + syncwarp. Cuts ~124 issue-cycles per
// iteration per warp (~11% of the issue budget; issue port was ~92%
// subscribed). Boundary segments (2/16) keep the zero-filling LDGSTS path.

__device__ __forceinline__ void prefetch_blk(const char* gsrc, int p0,
                                             unsigned sdst, int lane)
{
    #pragma unroll
    for (int j = 0; j < 16; ++j) {
        const int idx = j * 32 + lane;           // 16B chunk index in the 8KB blk
        const int p   = p0 + (idx >> 4);         // position this chunk belongs to
        const unsigned ok = (p >= 0 && p < W_DIM) ? 16u : 0u;
        asm volatile("cp.async.cg.shared.global [%0], [%1], 16, %2;"
                     :: "r"(sdst + idx * 16), "l"(gsrc + idx * 16), "r"(ok)
                     : "memory");
    }
    asm volatile("cp.async.commit_group;" ::: "memory");
}

#define LDS_STEP(u)                                                            \
    {                                                                          \
        xr[((u) + 8) & 15] = lds64(cons + (u) * 256);                          \
    }

#define STAGE1(u)                                                              \
    {                                                                          \
        u64 a0 = mul2(xr[((u) - 7) & 15], w1r[0]);                             \
        u64 a1 = mul2(xr[((u) - 6) & 15], w1r[1]);                             \
        a0 = fma2(xr[((u) - 5) & 15], w1r[2], a0);                             \
        a1 = fma2(xr[((u) - 4) & 15], w1r[3], a1);                             \
        a0 = fma2(xr[((u) - 3) & 15], w1r[4], a0);                             \
        a1 = fma2(xr[((u) - 2) & 15], w1r[5], a1);                             \
        a0 = fma2(xr[((u) - 1) & 15], w1r[6], a0);                             \
        a1 = fma2(xr[((u) - 0) & 15], w1r[7], a1);                             \
        u64 y1v = relu2(add2(a0, a1));                                         \
        if (BOUNDARY) {                                                        \
            const int p1 = pb + (u) - 4;                                       \
            if (p1 < 0 || p1 >= W_DIM) y1v = 0ull;                             \
        }                                                                      \
        y1r[(u) & 15] = y1v;                                                   \
    }

#define STAGE2(u)                                                              \
    {                                                                          \
        u64 b0 = mul2(y1r[((u) - 15) & 15], w2r[0]);                           \
        u64 b1 = mul2(y1r[((u) - 13) & 15], w2r[1]);                           \
        b0 = fma2(y1r[((u) - 11) & 15], w2r[2], b0);                           \
        b1 = fma2(y1r[((u) -  9) & 15], w2r[3], b1);                           \
        b0 = fma2(y1r[((u) -  7) & 15], w2r[4], b0);                           \
        b1 = fma2(y1r[((u) -  5) & 15], w2r[5], b1);                           \
        b0 = fma2(y1r[((u) -  3) & 15], w2r[6], b0);                           \
        b1 = fma2(y1r[((u) -  1) & 15], w2r[7], b1);                           \
        u64 y2v = relu2(add2(b0, b1));                                         \
        if (BOUNDARY) {                                                        \
            const int p2 = pb + (u) - 12;                                      \
            if (p2 < 0 || p2 >= W_DIM) y2v = 0ull;                             \
        }                                                                      \
        y2r[(u) & 31] = y2v;                                                   \
    }

#define STAGE3_STORE(u)                                                        \
    {                                                                          \
        u64 c0 = mul2(y2r[((u) - 30) & 31], w3r[0]);                           \
        u64 c1 = mul2(y2r[((u) - 26) & 31], w3r[1]);                           \
        c0 = fma2(y2r[((u) - 22) & 31], w3r[2], c0);                           \
        c1 = fma2(y2r[((u) - 18) & 31], w3r[3], c1);                           \
        c0 = fma2(y2r[((u) - 14) & 31], w3r[4], c0);                           \
        c1 = fma2(y2r[((u) - 10) & 31], w3r[5], c1);                           \
        c0 = fma2(y2r[((u) -  6) & 31], w3r[6], c0);                           \
        c1 = fma2(y2r[((u) -  2) & 31], w3r[7], c1);                           \
        const u64 y3v = relu2(add2(c0, c1));                                   \
        __stcs((u64*)(sp + (u) * C_DIM), y3v);                                 \
    }

#define COMPUTE_ITER(k)                                                        \
    {                                                                          \
        if ((k) == 0) {                                                        \
            _Pragma("unroll")                                                  \
            for (int u = 0; u < 32; ++u) {                                     \
                LDS_STEP(u) STAGE1(u)                                          \
            }                                                                  \
        } else if ((k) < WU_IT) {                                              \
            _Pragma("unroll")                                                  \
            for (int u = 0; u < 32; ++u) {                                     \
                LDS_STEP(u) STAGE1(u) STAGE2(u)                                \
            }                                                                  \
        } else {                                                               \
            _Pragma("unroll")                                                  \
            for (int u = 0; u < 32; ++u) {                                     \
                LDS_STEP(u) STAGE1(u) STAGE2(u) STAGE3_STORE(u)                \
            }                                                                  \
            sp += 32 * C_DIM;                                                  \
        }                                                                      \
    }

// ---- interior path: bulk TMA feed, no boundary masks ----
__device__ __forceinline__ void run_seg_tma(
    const float* __restrict__ x,
    const u64* w1r, const u64* w2r, const u64* w3r,
    float* __restrict__ out,
    int bh, int seg, int lane, unsigned wsm)
{
    constexpr bool BOUNDARY = false;
    const int s0 = seg * L_SEG;
    const int t0 = s0 - 36;
    const int pb = 0; (void)pb;                  // unused (no masks)

    const unsigned mb = wsm + MB_OFF;            // 3 mbarriers (8B each)

    if (lane == 0) {
        MBAR_INIT(mb + 0);
        MBAR_INIT(mb + 8);
        MBAR_INIT(mb + 16);
        MBAR_FENCE_INIT();
    }
    __syncwarp();

    // bulk stream: blk b = positions t0+8+32b .. t0+39+32b = one 8KB gmem range
    const char* gpf = (const char*)x
                    + ((long long)bh * W_DIM + (t0 + 8)) * (C_DIM * 4);

    if (lane == 0) {
        #pragma unroll
        for (int b = 0; b < DEPTH; ++b) {
            MBAR_EXPECT(mb + b * 8, (unsigned)BLK_BYTES);
            TMA_BULK(wsm + b * BLK_BYTES, gpf, (unsigned)BLK_BYTES, mb + b * 8);
            gpf += BLK_BYTES;
        }
    } else {
        gpf += DEPTH * BLK_BYTES;
    }

    float* sp = out + ((long long)bh * W_DIM + s0) * C_DIM + 2 * lane;

    u64 xr[16], y1r[16], y2r[32];
    #pragma unroll
    for (int j = 0; j < 16; ++j) xr[j]  = 0ull;
    #pragma unroll
    for (int j = 0; j < 16; ++j) y1r[j] = 0ull;
    #pragma unroll
    for (int j = 0; j < 32; ++j) y2r[j] = 0ull;

    unsigned cons = wsm + lane * 8;              // slot 0 base + lane offset
    const unsigned cons_hi = wsm + DEPTH * BLK_BYTES;

    int sidx = 0;                                // ring slot = k % 3
    int prt  = 0;                                // parity = (k/3) & 1

    for (int k = 0; k < N_IT; ++k) {
        MBAR_WAIT(mb + sidx * 8, prt);           // blk k ready (acquire)

        COMPUTE_ITER(k)

        if (k + DEPTH < N_IT && lane == 0) {     // refill slot with blk k+3
            MBAR_EXPECT(mb + sidx * 8, (unsigned)BLK_BYTES);
            TMA_BULK(cons - lane * 8, gpf, (unsigned)BLK_BYTES, mb + sidx * 8);
        }
        gpf += BLK_BYTES;

        cons += BLK_BYTES; if (cons >= cons_hi) cons -= DEPTH * BLK_BYTES;
        if (++sidx == DEPTH) { sidx = 0; prt ^= 1; }
    }
}

// ---- boundary path: LDGSTS with zero-fill (R12 verbatim) ----
__device__ __forceinline__ void run_seg_bdy(
    const float* __restrict__ x,
    const u64* w1r, const u64* w2r, const u64* w3r,
    float* __restrict__ out,
    int bh, int seg, int lane, unsigned wsm)
{
    constexpr bool BOUNDARY = true;
    const int s0 = seg * L_SEG;
    const int t0 = s0 - 36;

    const char* gpf = (const char*)x
                    + ((long long)bh * W_DIM + (t0 + 8)) * (C_DIM * 4);
    int ppf = t0 + 8;

    #pragma unroll
    for (int b = 0; b < DEPTH; ++b) {
        prefetch_blk(gpf, ppf, wsm + b * BLK_BYTES, lane);
        gpf += BLK_BYTES;
        ppf += 32;
    }

    float* sp = out + ((long long)bh * W_DIM + s0) * C_DIM + 2 * lane;
    int pb = t0;

    u64 xr[16], y1r[16], y2r[32];
    #pragma unroll
    for (int j = 0; j < 16; ++j) xr[j]  = 0ull;
    #pragma unroll
    for (int j = 0; j < 16; ++j) y1r[j] = 0ull;
    #pragma unroll
    for (int j = 0; j < 32; ++j) y2r[j] = 0ull;

    unsigned cons = wsm + lane * 8;
    const unsigned cons_hi = wsm + DEPTH * BLK_BYTES;

    for (int k = 0; k < N_IT; ++k) {
        if      (k >= N_IT - 1) asm volatile("cp.async.wait_group 0;" ::: "memory");
        else if (k == N_IT - 2) asm volatile("cp.async.wait_group 1;" ::: "memory");
        else                    asm volatile("cp.async.wait_group 2;" ::: "memory");
        __syncwarp();

        COMPUTE_ITER(k)

        if (k + DEPTH < N_IT) {
            prefetch_blk(gpf, ppf, cons - lane * 8, lane);
            gpf += BLK_BYTES;
            ppf += 32;
        }

        cons += BLK_BYTES; if (cons >= cons_hi) cons -= DEPTH * BLK_BYTES;
        pb += 32;
    }
}

__global__ void __launch_bounds__(32)
conv_stack_kernel(const float* __restrict__ x,
                  const float* __restrict__ w1,
                  const float* __restrict__ w2,
                  const float* __restrict__ w3,
                  float* __restrict__ out)
{
    extern __shared__ char smem[];

    const int lane = threadIdx.x & 31;
    const unsigned wsm = (unsigned)__cvta_generic_to_shared(smem);

    const int s   = blockIdx.x;
    const int bh  = s >> 4;        // s / SEGS
    const int seg = s & 15;        // s % SEGS

    u64 w1r[8], w2r[8], w3r[8];
    #pragma unroll
    for (int k = 0; k < 8; ++k) {
        w1r[k] = *(const u64*)(w1 + k * C_DIM + 2 * lane);
        w2r[k] = *(const u64*)(w2 + k * C_DIM + 2 * lane);
        w3r[k] = *(const u64*)(w3 + k * C_DIM + 2 * lane);
    }

    if (seg == 0 || seg == SEGS - 1) {
        run_seg_bdy(x, w1r, w2r, w3r, out, bh, seg, lane, wsm);
    } else {
        run_seg_tma(x, w1r, w2r, w3r, out, bh, seg, lane, wsm);
    }
}

extern "C" void kernel_launch(void* const* d_in, const int* in_sizes, int n_in,
                              void* d_out, int out_size)
{
    const float* x  = (const float*)d_in[0];
    const float* w1 = (const float*)d_in[1];
    const float* w2 = (const float*)d_in[2];
    const float* w3 = (const float*)d_in[3];
    float* out = (float*)d_out;

    (void)in_sizes; (void)n_in; (void)out_size;

    cudaFuncSetAttribute(conv_stack_kernel,
                         cudaFuncAttributeMaxDynamicSharedMemorySize, WARP_SMEM);

    // 336 rows * 16 segs = 5376 one-warp blocks
    conv_stack_kernel<<<N_SEG, 32, WARP_SMEM>>>(x, w1, w2, w3, out);
}